// round 4
// baseline (speedup 1.0000x reference)
#include <cuda_runtime.h>
#include <cuda_bf16.h>
#include <cstdint>

// MaskedAttention: B=4, S=1024, WIDTH=1024, H=16, DH=64
// Head-axis softmax. GEMMs: bf16 3-term split on tensor cores, with inputs
// pre-split to bf16 hi/lo arrays and cp.async double-buffered mainloops.

#define B_ 4
#define S_ 1024
#define W_ 1024
#define H_ 16
#define DH_ 64
#define M_ (B_ * S_)

// ---------------- device scratch (allocation-free rule) --------------------
__device__ __nv_bfloat16 g_inp_h[M_ * W_], g_inp_l[M_ * W_];
__device__ __nv_bfloat16 g_wq_h[W_ * W_],  g_wq_l[W_ * W_];
__device__ __nv_bfloat16 g_wk_h[W_ * W_],  g_wk_l[W_ * W_];
__device__ __nv_bfloat16 g_wv_h[W_ * W_],  g_wv_l[W_ * W_];
__device__ __nv_bfloat16 g_wo_h[W_ * W_],  g_wo_l[W_ * W_];
__device__ __nv_bfloat16 g_q_h[M_ * W_],   g_q_l[M_ * W_];
__device__ __nv_bfloat16 g_k_h[M_ * W_],   g_k_l[M_ * W_];
__device__ __nv_bfloat16 g_vt_h[B_ * H_ * DH_ * S_], g_vt_l[B_ * H_ * DH_ * S_];
__device__ __nv_bfloat16 g_x_h[M_ * W_],   g_x_l[M_ * W_];
__device__ float g_qk[(size_t)B_ * H_ * S_ * S_];                     // 256 MB
__device__ __nv_bfloat16 g_at_h[(size_t)B_ * H_ * S_ * S_];           // 128 MB
__device__ __nv_bfloat16 g_at_l[(size_t)B_ * H_ * S_ * S_];           // 128 MB

// ---------------- helpers --------------------------------------------------
__device__ __forceinline__ void mma_bf16(float* c, const uint32_t* a, const uint32_t* b) {
    asm volatile(
        "mma.sync.aligned.m16n8k16.row.col.f32.bf16.bf16.f32 "
        "{%0,%1,%2,%3}, {%4,%5,%6,%7}, {%8,%9}, {%0,%1,%2,%3};"
        : "+f"(c[0]), "+f"(c[1]), "+f"(c[2]), "+f"(c[3])
        : "r"(a[0]), "r"(a[1]), "r"(a[2]), "r"(a[3]), "r"(b[0]), "r"(b[1]));
}

__device__ __forceinline__ void split_pack(float x, float y, uint32_t& hi, uint32_t& lo) {
    __nv_bfloat16 hx = __float2bfloat16(x);
    __nv_bfloat16 hy = __float2bfloat16(y);
    __nv_bfloat16 lx = __float2bfloat16(x - __bfloat162float(hx));
    __nv_bfloat16 ly = __float2bfloat16(y - __bfloat162float(hy));
    __nv_bfloat162 hp = __halves2bfloat162(hx, hy);
    __nv_bfloat162 lp = __halves2bfloat162(lx, ly);
    hi = *reinterpret_cast<uint32_t*>(&hp);
    lo = *reinterpret_cast<uint32_t*>(&lp);
}

__device__ __forceinline__ void split1(float x, __nv_bfloat16& h, __nv_bfloat16& l) {
    h = __float2bfloat16(x);
    l = __float2bfloat16(x - __bfloat162float(h));
}

#define CP16(dst_u32, src_ptr) \
    asm volatile("cp.async.cg.shared.global [%0], [%1], 16;" :: "r"(dst_u32), "l"(src_ptr))

// ---------------------------------------------------------------------------
// bf16 GEMM core: C[m,n] = scale * sum_k (Ah+Al)[m,k] * (Bh+Bl)[n,k] (+bias)
// 128(M) x BN(N) block tile, K-tile 32, 256 threads (8 warps: 4m x 2n).
// cp.async double-buffered. Smem rows: 16 u32 (32 bf16) + 4 pad = 20 stride.
// MODE 0: fp32 C. MODE 1: split hi/lo C (packed bf16x2). MODE 2: vt scatter.
// ---------------------------------------------------------------------------
template <int BN, int MODE>
__device__ __forceinline__ void gemm_core(
        const __nv_bfloat16* __restrict__ Ah, const __nv_bfloat16* __restrict__ Al, int lda,
        const __nv_bfloat16* __restrict__ Bh, const __nv_bfloat16* __restrict__ Bl, int ldb,
        int K, float scale, const float* __restrict__ bias,
        float* __restrict__ Cf, uint32_t* __restrict__ Ch, uint32_t* __restrict__ Cl,
        int ldc, __nv_bfloat16* __restrict__ Vh, __nv_bfloat16* __restrict__ Vl) {
    constexpr int NT = BN / 16;
    constexpr int A_ST = 128 * 20;
    constexpr int B_ST = BN * 20;
    extern __shared__ __align__(16) uint32_t sm[];
    uint32_t* AH = sm;                         // [2][A_ST]
    uint32_t* AL = sm + 2 * A_ST;
    uint32_t* BH = sm + 4 * A_ST;              // [2][B_ST]
    uint32_t* BL = sm + 4 * A_ST + 2 * B_ST;

    const int tid = threadIdx.x;
    const int lane = tid & 31, warp = tid >> 5;
    const int gid = lane >> 2, tig = lane & 3;
    const int wm = warp >> 1, wn = warp & 1;
    const int m0w = wm * 32, n0w = wn * (BN / 2);
    const int row0 = blockIdx.y * 128;
    const int col0 = blockIdx.x * BN;

    float acc[2][NT][4] = {};

    auto load_stage = [&](int st, int k0) {
        #pragma unroll
        for (int it = 0; it < 2; it++) {               // A: 512 chunks of 16B
            int c = tid + it * 256;
            int r = c >> 2, ck = c & 3;
            size_t off = (size_t)(row0 + r) * lda + k0 + ck * 8;
            uint32_t dh = (uint32_t)__cvta_generic_to_shared(&AH[st * A_ST + r * 20 + ck * 4]);
            uint32_t dl = (uint32_t)__cvta_generic_to_shared(&AL[st * A_ST + r * 20 + ck * 4]);
            CP16(dh, Ah + off);
            CP16(dl, Al + off);
        }
        #pragma unroll
        for (int it = 0; it < BN / 64; it++) {         // B: BN*4 chunks
            int c = tid + it * 256;
            int r = c >> 2, ck = c & 3;
            size_t off = (size_t)(col0 + r) * ldb + k0 + ck * 8;
            uint32_t dh = (uint32_t)__cvta_generic_to_shared(&BH[st * B_ST + r * 20 + ck * 4]);
            uint32_t dl = (uint32_t)__cvta_generic_to_shared(&BL[st * B_ST + r * 20 + ck * 4]);
            CP16(dh, Bh + off);
            CP16(dl, Bl + off);
        }
    };

    const int nk = K / 32;
    load_stage(0, 0);
    asm volatile("cp.async.commit_group;");

    for (int t = 0; t < nk; t++) {
        const int st = t & 1;
        if (t + 1 < nk) {
            load_stage(st ^ 1, (t + 1) * 32);
            asm volatile("cp.async.commit_group;");
            asm volatile("cp.async.wait_group 1;");
        } else {
            asm volatile("cp.async.wait_group 0;");
        }
        __syncthreads();

        const uint32_t* aH = AH + st * A_ST;
        const uint32_t* aL = AL + st * A_ST;
        const uint32_t* bHs = BH + st * B_ST;
        const uint32_t* bLs = BL + st * B_ST;

        #pragma unroll
        for (int ks = 0; ks < 2; ks++) {
            const int kb = ks * 8;
            uint32_t ah[2][4], al[2][4], bh[NT][2];
            #pragma unroll
            for (int mi = 0; mi < 2; mi++) {
                int rb = (m0w + mi * 16 + gid) * 20 + kb;
                ah[mi][0] = aH[rb + tig];
                ah[mi][1] = aH[rb + 8 * 20 + tig];
                ah[mi][2] = aH[rb + tig + 4];
                ah[mi][3] = aH[rb + 8 * 20 + tig + 4];
                al[mi][0] = aL[rb + tig];
                al[mi][1] = aL[rb + 8 * 20 + tig];
                al[mi][2] = aL[rb + tig + 4];
                al[mi][3] = aL[rb + 8 * 20 + tig + 4];
            }
            #pragma unroll
            for (int ni = 0; ni < NT; ni++) {
                int rb = (n0w + ni * 8 + gid) * 20 + kb;
                bh[ni][0] = bHs[rb + tig];
                bh[ni][1] = bHs[rb + tig + 4];
            }
            #pragma unroll
            for (int mi = 0; mi < 2; mi++)
                #pragma unroll
                for (int ni = 0; ni < NT; ni++)
                    mma_bf16(acc[mi][ni], ah[mi], bh[ni]);
            #pragma unroll
            for (int mi = 0; mi < 2; mi++)
                #pragma unroll
                for (int ni = 0; ni < NT; ni++)
                    mma_bf16(acc[mi][ni], al[mi], bh[ni]);
            uint32_t bl[NT][2];
            #pragma unroll
            for (int ni = 0; ni < NT; ni++) {
                int rb = (n0w + ni * 8 + gid) * 20 + kb;
                bl[ni][0] = bLs[rb + tig];
                bl[ni][1] = bLs[rb + tig + 4];
            }
            #pragma unroll
            for (int mi = 0; mi < 2; mi++)
                #pragma unroll
                for (int ni = 0; ni < NT; ni++)
                    mma_bf16(acc[mi][ni], ah[mi], bl[ni]);
        }
        __syncthreads();
    }

    // epilogue
    #pragma unroll
    for (int mi = 0; mi < 2; mi++) {
        #pragma unroll
        for (int ni = 0; ni < NT; ni++) {
            int row = row0 + m0w + mi * 16 + gid;
            int col = col0 + n0w + ni * 8 + tig * 2;
            float b0 = bias ? bias[col] : 0.0f;
            float b1 = bias ? bias[col + 1] : 0.0f;
            float v0 = acc[mi][ni][0] * scale + b0;
            float v1 = acc[mi][ni][1] * scale + b1;
            float v2 = acc[mi][ni][2] * scale + b0;
            float v3 = acc[mi][ni][3] * scale + b1;
            if (MODE == 0) {
                float2 o0 = {v0, v1}, o1 = {v2, v3};
                *(float2*)&Cf[(size_t)row * ldc + col] = o0;
                *(float2*)&Cf[(size_t)(row + 8) * ldc + col] = o1;
            } else if (MODE == 1) {
                uint32_t h0, l0, h1, l1;
                split_pack(v0, v1, h0, l0);
                split_pack(v2, v3, h1, l1);
                size_t i0 = ((size_t)row * ldc + col) >> 1;
                size_t i1 = ((size_t)(row + 8) * ldc + col) >> 1;
                Ch[i0] = h0; Cl[i0] = l0;
                Ch[i1] = h1; Cl[i1] = l1;
            } else {
                // V-transpose scatter: row = b*S+s, col = h*64+d -> vt[bh][d][s]
                int b = row >> 10, s = row & 1023;
                int h = col >> 6, d = col & 63;
                size_t base = ((size_t)(b * 16 + h) * 64 + d) * S_;
                __nv_bfloat16 hh, ll;
                split1(v0, hh, ll); Vh[base + s] = hh;        Vl[base + s] = ll;
                split1(v1, hh, ll); Vh[base + S_ + s] = hh;   Vl[base + S_ + s] = ll;
                split1(v2, hh, ll); Vh[base + s + 8] = hh;    Vl[base + s + 8] = ll;
                split1(v3, hh, ll); Vh[base + S_ + s + 8] = hh; Vl[base + S_ + s + 8] = ll;
            }
        }
    }
}

// ---------------- kernel wrappers ------------------------------------------
__global__ __launch_bounds__(256) void split_kernel(
        const float* __restrict__ src, uint32_t* __restrict__ hi,
        uint32_t* __restrict__ lo, int n4) {
    int idx = blockIdx.x * blockDim.x + threadIdx.x;
    if (idx >= n4) return;
    float4 v = ((const float4*)src)[idx];
    uint32_t h0, l0, h1, l1;
    split_pack(v.x, v.y, h0, l0);
    split_pack(v.z, v.w, h1, l1);
    uint2 hp = {h0, h1}, lp = {l0, l1};
    ((uint2*)hi)[idx] = hp;
    ((uint2*)lo)[idx] = lp;
}

__global__ __launch_bounds__(256) void proj_split_kernel(
        const __nv_bfloat16* Ah, const __nv_bfloat16* Al,
        const __nv_bfloat16* Bh, const __nv_bfloat16* Bl,
        const float* bias, uint32_t* Ch, uint32_t* Cl) {
    gemm_core<128, 1>(Ah, Al, W_, Bh, Bl, W_, W_, 1.0f, bias,
                      nullptr, Ch, Cl, W_, nullptr, nullptr);
}

__global__ __launch_bounds__(256) void proj_vt_kernel(
        const __nv_bfloat16* Ah, const __nv_bfloat16* Al,
        const __nv_bfloat16* Bh, const __nv_bfloat16* Bl,
        const float* bias, __nv_bfloat16* Vh, __nv_bfloat16* Vl) {
    gemm_core<128, 2>(Ah, Al, W_, Bh, Bl, W_, W_, 1.0f, bias,
                      nullptr, nullptr, nullptr, 0, Vh, Vl);
}

__global__ __launch_bounds__(256) void qk_kernel(
        const __nv_bfloat16* qh, const __nv_bfloat16* ql,
        const __nv_bfloat16* kh, const __nv_bfloat16* kl,
        float* __restrict__ out) {
    const int bh = blockIdx.z;
    const int b = bh >> 4, h = bh & 15;
    size_t off = (size_t)b * S_ * W_ + h * DH_;
    gemm_core<128, 0>(qh + off, ql + off, W_, kh + off, kl + off, W_,
                      DH_, 0.125f, nullptr,
                      out + (size_t)bh * S_ * S_, nullptr, nullptr, S_,
                      nullptr, nullptr);
}

__global__ __launch_bounds__(256) void av_kernel(
        const __nv_bfloat16* ah, const __nv_bfloat16* al,
        const __nv_bfloat16* vh, const __nv_bfloat16* vl,
        uint32_t* xh, uint32_t* xl) {
    const int bh = blockIdx.z;
    const int b = bh >> 4, h = bh & 15;
    size_t aoff = (size_t)bh * S_ * S_;
    size_t voff = (size_t)bh * DH_ * S_;
    size_t xoff = ((size_t)b * S_ * W_ + h * DH_) >> 1;
    gemm_core<64, 1>(ah + aoff, al + aoff, S_, vh + voff, vl + voff, S_,
                     S_, 1.0f, nullptr,
                     nullptr, xh + xoff, xl + xoff, W_, nullptr, nullptr);
}

__global__ __launch_bounds__(256) void out_kernel(
        const __nv_bfloat16* Ah, const __nv_bfloat16* Al,
        const __nv_bfloat16* Bh, const __nv_bfloat16* Bl,
        const float* bias, float* C) {
    gemm_core<128, 0>(Ah, Al, W_, Bh, Bl, W_, W_, 1.0f, bias,
                      C, nullptr, nullptr, W_, nullptr, nullptr);
}

// ---------------------------------------------------------------------------
// Head-axis softmax: read fp32 scores, write split-bf16 attn.
// Masked (b,q,k): all 16 logits equal -> uniform 1/16.
// ---------------------------------------------------------------------------
__global__ __launch_bounds__(256) void head_softmax_kernel(
        const int* __restrict__ mask, const float* __restrict__ qk,
        uint32_t* __restrict__ ath, uint32_t* __restrict__ atl) {
    const int idx = blockIdx.x * blockDim.x + threadIdx.x;   // over B*S*S/4
    const int b = idx >> 18;
    const int qs4 = idx & ((1 << 18) - 1);
    const size_t base = (size_t)b * H_ * S_ * S_ + (size_t)qs4 * 4;
    const size_t hs = (size_t)S_ * S_;

    int4 mv = ((const int4*)mask)[idx];
    int ms[4] = {mv.x, mv.y, mv.z, mv.w};

    float v[H_][4];
    #pragma unroll
    for (int h = 0; h < H_; h++) {
        float4 t = *(const float4*)&qk[base + h * hs];
        v[h][0] = t.x; v[h][1] = t.y; v[h][2] = t.z; v[h][3] = t.w;
    }

    #pragma unroll
    for (int l = 0; l < 4; l++) {
        if (ms[l] == 0) {
            #pragma unroll
            for (int h = 0; h < H_; h++) v[h][l] = 1.0f / 16.0f;
        } else {
            float mx = v[0][l];
            #pragma unroll
            for (int h = 1; h < H_; h++) mx = fmaxf(mx, v[h][l]);
            float s = 0.0f;
            #pragma unroll
            for (int h = 0; h < H_; h++) {
                v[h][l] = __expf(v[h][l] - mx);
                s += v[h][l];
            }
            float inv = 1.0f / s;
            #pragma unroll
            for (int h = 0; h < H_; h++) v[h][l] *= inv;
        }
    }

    #pragma unroll
    for (int h = 0; h < H_; h++) {
        uint32_t h0, l0, h1, l1;
        split_pack(v[h][0], v[h][1], h0, l0);
        split_pack(v[h][2], v[h][3], h1, l1);
        size_t i = (base + h * hs) >> 1;
        uint2 hp = {h0, h1}, lp = {l0, l1};
        *(uint2*)&ath[i] = hp;
        *(uint2*)&atl[i] = lp;
    }
}

// ---------------------------------------------------------------------------
extern "C" void kernel_launch(void* const* d_in, const int* in_sizes, int n_in,
                              void* d_out, int out_size) {
    const float* inp  = (const float*)d_in[0];
    const int*   mask = (const int*)  d_in[1];
    const float* wq   = (const float*)d_in[2];
    const float* bq   = (const float*)d_in[3];
    const float* wk   = (const float*)d_in[4];
    const float* bk   = (const float*)d_in[5];
    const float* wv   = (const float*)d_in[6];
    const float* bv   = (const float*)d_in[7];
    const float* wo   = (const float*)d_in[8];
    const float* bo   = (const float*)d_in[9];
    float* out = (float*)d_out;

    #define SYM(p, s) void* p; cudaGetSymbolAddress(&p, s)
    SYM(inp_h, g_inp_h); SYM(inp_l, g_inp_l);
    SYM(wq_h, g_wq_h);   SYM(wq_l, g_wq_l);
    SYM(wk_h, g_wk_h);   SYM(wk_l, g_wk_l);
    SYM(wv_h, g_wv_h);   SYM(wv_l, g_wv_l);
    SYM(wo_h, g_wo_h);   SYM(wo_l, g_wo_l);
    SYM(q_h, g_q_h);     SYM(q_l, g_q_l);
    SYM(k_h, g_k_h);     SYM(k_l, g_k_l);
    SYM(vt_h, g_vt_h);   SYM(vt_l, g_vt_l);
    SYM(x_h, g_x_h);     SYM(x_l, g_x_l);
    SYM(qkp, g_qk);
    SYM(at_h, g_at_h);   SYM(at_l, g_at_l);
    #undef SYM

    const int SMEM_BN128 = 81920;   // 4*(128*20)*2st*4B + ... = 80 KB
    const int SMEM_BN64  = 61440;   // 60 KB
    static bool attr_set = false;
    if (!attr_set) {
        cudaFuncSetAttribute(proj_split_kernel, cudaFuncAttributeMaxDynamicSharedMemorySize, SMEM_BN128);
        cudaFuncSetAttribute(proj_vt_kernel,    cudaFuncAttributeMaxDynamicSharedMemorySize, SMEM_BN128);
        cudaFuncSetAttribute(qk_kernel,         cudaFuncAttributeMaxDynamicSharedMemorySize, SMEM_BN128);
        cudaFuncSetAttribute(out_kernel,        cudaFuncAttributeMaxDynamicSharedMemorySize, SMEM_BN128);
        cudaFuncSetAttribute(av_kernel,         cudaFuncAttributeMaxDynamicSharedMemorySize, SMEM_BN64);
        attr_set = true;
    }

    // 1) split inputs/weights to bf16 hi/lo
    split_kernel<<<(M_ * W_ / 4) / 256, 256>>>(inp, (uint32_t*)inp_h, (uint32_t*)inp_l, M_ * W_ / 4);
    split_kernel<<<(W_ * W_ / 4) / 256, 256>>>(wq, (uint32_t*)wq_h, (uint32_t*)wq_l, W_ * W_ / 4);
    split_kernel<<<(W_ * W_ / 4) / 256, 256>>>(wk, (uint32_t*)wk_h, (uint32_t*)wk_l, W_ * W_ / 4);
    split_kernel<<<(W_ * W_ / 4) / 256, 256>>>(wv, (uint32_t*)wv_h, (uint32_t*)wv_l, W_ * W_ / 4);
    split_kernel<<<(W_ * W_ / 4) / 256, 256>>>(wo, (uint32_t*)wo_h, (uint32_t*)wo_l, W_ * W_ / 4);

    dim3 pg(W_ / 128, M_ / 128);   // (8, 32)
    // 2) projections (epilogues write split bf16 / vt scatter)
    proj_split_kernel<<<pg, 256, SMEM_BN128>>>(
        (const __nv_bfloat16*)inp_h, (const __nv_bfloat16*)inp_l,
        (const __nv_bfloat16*)wq_h,  (const __nv_bfloat16*)wq_l,
        bq, (uint32_t*)q_h, (uint32_t*)q_l);
    proj_split_kernel<<<pg, 256, SMEM_BN128>>>(
        (const __nv_bfloat16*)inp_h, (const __nv_bfloat16*)inp_l,
        (const __nv_bfloat16*)wk_h,  (const __nv_bfloat16*)wk_l,
        bk, (uint32_t*)k_h, (uint32_t*)k_l);
    proj_vt_kernel<<<pg, 256, SMEM_BN128>>>(
        (const __nv_bfloat16*)inp_h, (const __nv_bfloat16*)inp_l,
        (const __nv_bfloat16*)wv_h,  (const __nv_bfloat16*)wv_l,
        bv, (__nv_bfloat16*)vt_h, (__nv_bfloat16*)vt_l);

    // 3) QK^T
    dim3 qg(S_ / 128, S_ / 128, B_ * H_);   // (8, 8, 64)
    qk_kernel<<<qg, 256, SMEM_BN128>>>(
        (const __nv_bfloat16*)q_h, (const __nv_bfloat16*)q_l,
        (const __nv_bfloat16*)k_h, (const __nv_bfloat16*)k_l, (float*)qkp);

    // 4) head-axis softmax -> split bf16 attn
    head_softmax_kernel<<<(B_ * S_ * S_ / 4) / 256, 256>>>(
        mask, (const float*)qkp, (uint32_t*)at_h, (uint32_t*)at_l);

    // 5) attn @ V -> x (split bf16)
    dim3 ag(1, S_ / 128, B_ * H_);
    av_kernel<<<ag, 256, SMEM_BN64>>>(
        (const __nv_bfloat16*)at_h, (const __nv_bfloat16*)at_l,
        (const __nv_bfloat16*)vt_h, (const __nv_bfloat16*)vt_l,
        (uint32_t*)x_h, (uint32_t*)x_l);

    // 6) output projection (fp32 out + bias)
    out_kernel<<<pg, 256, SMEM_BN128>>>(
        (const __nv_bfloat16*)x_h, (const __nv_bfloat16*)x_l,
        (const __nv_bfloat16*)wo_h, (const __nv_bfloat16*)wo_l,
        bo, out);
}

// round 6
// speedup vs baseline: 1.0435x; 1.0435x over previous
#include <cuda_runtime.h>
#include <cuda_bf16.h>
#include <cstdint>

// MaskedAttention: B=4, S=1024, WIDTH=1024, H=16, DH=64
// Head-axis softmax. GEMMs: bf16 3-term split (hi*hi + lo*hi + hi*lo) on
// tensor cores; inputs pre-split to bf16 hi/lo; cp.async double buffering;
// ldmatrix.x4 fragment loads; coalesced epilogues.

#define B_ 4
#define S_ 1024
#define W_ 1024
#define H_ 16
#define DH_ 64
#define M_ (B_ * S_)

// ---------------- device scratch (allocation-free rule) --------------------
__device__ __nv_bfloat16 g_inp_h[M_ * W_], g_inp_l[M_ * W_];
__device__ __nv_bfloat16 g_wq_h[W_ * W_],  g_wq_l[W_ * W_];
__device__ __nv_bfloat16 g_wk_h[W_ * W_],  g_wk_l[W_ * W_];
__device__ __nv_bfloat16 g_wv_h[W_ * W_],  g_wv_l[W_ * W_];
__device__ __nv_bfloat16 g_wo_h[W_ * W_],  g_wo_l[W_ * W_];
__device__ __nv_bfloat16 g_q_h[M_ * W_],   g_q_l[M_ * W_];
__device__ __nv_bfloat16 g_k_h[M_ * W_],   g_k_l[M_ * W_];
__device__ __nv_bfloat16 g_vt_h[B_ * H_ * DH_ * S_], g_vt_l[B_ * H_ * DH_ * S_];
__device__ __nv_bfloat16 g_x_h[M_ * W_],   g_x_l[M_ * W_];
__device__ float g_qk[(size_t)B_ * H_ * S_ * S_];                     // 256 MB
__device__ __nv_bfloat16 g_at_h[(size_t)B_ * H_ * S_ * S_];           // 128 MB
__device__ __nv_bfloat16 g_at_l[(size_t)B_ * H_ * S_ * S_];           // 128 MB

// ---------------- helpers --------------------------------------------------
__device__ __forceinline__ void mma_bf16(float* c, const uint32_t* a, const uint32_t* b) {
    asm volatile(
        "mma.sync.aligned.m16n8k16.row.col.f32.bf16.bf16.f32 "
        "{%0,%1,%2,%3}, {%4,%5,%6,%7}, {%8,%9}, {%0,%1,%2,%3};"
        : "+f"(c[0]), "+f"(c[1]), "+f"(c[2]), "+f"(c[3])
        : "r"(a[0]), "r"(a[1]), "r"(a[2]), "r"(a[3]), "r"(b[0]), "r"(b[1]));
}

__device__ __forceinline__ void ldsm4(uint32_t* r, uint32_t saddr) {
    asm volatile("ldmatrix.sync.aligned.m8n8.x4.shared.b16 {%0,%1,%2,%3}, [%4];"
                 : "=r"(r[0]), "=r"(r[1]), "=r"(r[2]), "=r"(r[3]) : "r"(saddr));
}

__device__ __forceinline__ void split_pack(float x, float y, uint32_t& hi, uint32_t& lo) {
    __nv_bfloat16 hx = __float2bfloat16(x);
    __nv_bfloat16 hy = __float2bfloat16(y);
    __nv_bfloat16 lx = __float2bfloat16(x - __bfloat162float(hx));
    __nv_bfloat16 ly = __float2bfloat16(y - __bfloat162float(hy));
    __nv_bfloat162 hp = __halves2bfloat162(hx, hy);
    __nv_bfloat162 lp = __halves2bfloat162(lx, ly);
    hi = *reinterpret_cast<uint32_t*>(&hp);
    lo = *reinterpret_cast<uint32_t*>(&lp);
}

#define CP16(dst_u32, src_ptr) \
    asm volatile("cp.async.cg.shared.global [%0], [%1], 16;" :: "r"(dst_u32), "l"(src_ptr))

// ---------------------------------------------------------------------------
// bf16 GEMM core: C[m,n] = scale * sum_k (Ah+Al)[m,k] * (Bh+Bl)[n,k] (+bias)
// 128(M) x BN(N) block tile, K-tile 32, 256 threads (8 warps: 4m x 2n).
// cp.async double-buffered; ldmatrix.x4 fragment loads.
// Smem rows: 16 u32 (32 bf16) + 4 pad = 20 u32 stride (LDSM conflict-free).
// MODE 0: fp32 C. MODE 1: split hi/lo C (packed bf16x2).
// MODE 2: vt transpose via smem staging -> coalesced packed stores.
// ---------------------------------------------------------------------------
template <int BN, int MODE>
__device__ __forceinline__ void gemm_core(
        const __nv_bfloat16* __restrict__ Ah, const __nv_bfloat16* __restrict__ Al, int lda,
        const __nv_bfloat16* __restrict__ Bh, const __nv_bfloat16* __restrict__ Bl, int ldb,
        int K, float scale, const float* __restrict__ bias,
        float* __restrict__ Cf, uint32_t* __restrict__ Ch, uint32_t* __restrict__ Cl,
        int ldc, __nv_bfloat16* __restrict__ Vh, __nv_bfloat16* __restrict__ Vl) {
    constexpr int NT = BN / 16;
    constexpr int A_ST = 128 * 20;
    constexpr int B_ST = BN * 20;
    extern __shared__ __align__(16) uint32_t sm[];
    uint32_t* AH = sm;                         // [2][A_ST]
    uint32_t* AL = sm + 2 * A_ST;
    uint32_t* BH = sm + 4 * A_ST;              // [2][B_ST]
    uint32_t* BL = sm + 4 * A_ST + 2 * B_ST;

    const int tid = threadIdx.x;
    const int lane = tid & 31, warp = tid >> 5;
    const int gid = lane >> 2, tig = lane & 3;
    const int wm = warp >> 1, wn = warp & 1;
    const int m0w = wm * 32, n0w = wn * (BN / 2);
    const int row0 = blockIdx.y * 128;
    const int col0 = blockIdx.x * BN;

    // ldmatrix per-lane address components (u32 indices into a stage)
    const int a_row = m0w + ((lane >> 3) & 1) * 8 + (lane & 7);
    const int a_coff = (lane >> 4) * 4;
    const int b_row = n0w + ((lane >> 4) & 1) * 8 + (lane & 7);
    const int b_coff = ((lane >> 3) & 1) * 4;

    const uint32_t sAH = (uint32_t)__cvta_generic_to_shared(AH);
    const uint32_t sAL = (uint32_t)__cvta_generic_to_shared(AL);
    const uint32_t sBH = (uint32_t)__cvta_generic_to_shared(BH);
    const uint32_t sBL = (uint32_t)__cvta_generic_to_shared(BL);

    float acc[2][NT][4] = {};

    auto load_stage = [&](int st, int k0) {
        #pragma unroll
        for (int it = 0; it < 2; it++) {               // A: 512 chunks of 16B
            int c = tid + it * 256;
            int r = c >> 2, ck = c & 3;
            size_t off = (size_t)(row0 + r) * lda + k0 + ck * 8;
            uint32_t dh = sAH + (st * A_ST + r * 20 + ck * 4) * 4;
            uint32_t dl = sAL + (st * A_ST + r * 20 + ck * 4) * 4;
            CP16(dh, Ah + off);
            CP16(dl, Al + off);
        }
        #pragma unroll
        for (int it = 0; it < BN / 64; it++) {         // B: BN*4 chunks
            int c = tid + it * 256;
            int r = c >> 2, ck = c & 3;
            size_t off = (size_t)(col0 + r) * ldb + k0 + ck * 8;
            uint32_t dh = sBH + (st * B_ST + r * 20 + ck * 4) * 4;
            uint32_t dl = sBL + (st * B_ST + r * 20 + ck * 4) * 4;
            CP16(dh, Bh + off);
            CP16(dl, Bl + off);
        }
    };

    const int nk = K / 32;
    load_stage(0, 0);
    asm volatile("cp.async.commit_group;");

    for (int t = 0; t < nk; t++) {
        const int st = t & 1;
        if (t + 1 < nk) {
            load_stage(st ^ 1, (t + 1) * 32);
            asm volatile("cp.async.commit_group;");
            asm volatile("cp.async.wait_group 1;");
        } else {
            asm volatile("cp.async.wait_group 0;");
        }
        __syncthreads();

        #pragma unroll
        for (int ks = 0; ks < 2; ks++) {
            const int kb = ks * 8;
            const uint32_t aoff = (uint32_t)(st * A_ST + a_row * 20 + kb + a_coff) * 4;
            const uint32_t boff = (uint32_t)(st * B_ST + b_row * 20 + kb + b_coff) * 4;

            uint32_t ah[2][4], al[2][4], bh[NT][2];
            #pragma unroll
            for (int mi = 0; mi < 2; mi++) {
                ldsm4(ah[mi], sAH + aoff + mi * (16 * 20 * 4));
                ldsm4(al[mi], sAL + aoff + mi * (16 * 20 * 4));
            }
            #pragma unroll
            for (int np = 0; np < NT / 2; np++) {
                uint32_t r[4];
                ldsm4(r, sBH + boff + np * (16 * 20 * 4));
                bh[np * 2][0] = r[0]; bh[np * 2][1] = r[1];
                bh[np * 2 + 1][0] = r[2]; bh[np * 2 + 1][1] = r[3];
            }
            // pass 1: hi*hi   pass 2: lo*hi
            #pragma unroll
            for (int mi = 0; mi < 2; mi++)
                #pragma unroll
                for (int ni = 0; ni < NT; ni++)
                    mma_bf16(acc[mi][ni], ah[mi], bh[ni]);
            #pragma unroll
            for (int mi = 0; mi < 2; mi++)
                #pragma unroll
                for (int ni = 0; ni < NT; ni++)
                    mma_bf16(acc[mi][ni], al[mi], bh[ni]);
            // pass 3: hi*lo
            uint32_t bl[NT][2];
            #pragma unroll
            for (int np = 0; np < NT / 2; np++) {
                uint32_t r[4];
                ldsm4(r, sBL + boff + np * (16 * 20 * 4));
                bl[np * 2][0] = r[0]; bl[np * 2][1] = r[1];
                bl[np * 2 + 1][0] = r[2]; bl[np * 2 + 1][1] = r[3];
            }
            #pragma unroll
            for (int mi = 0; mi < 2; mi++)
                #pragma unroll
                for (int ni = 0; ni < NT; ni++)
                    mma_bf16(acc[mi][ni], ah[mi], bl[ni]);
        }
        __syncthreads();
    }

    // ---------------- epilogue ----------------
    if (MODE == 2) {
        // stage fp32 C in smem (reuse operand smem), then transposed coalesced
        // writes into vt[bh][d][s] as split bf16.
        float* cs = (float*)sm;            // 128 x 132 floats = 67.6 KB
        #pragma unroll
        for (int mi = 0; mi < 2; mi++)
            #pragma unroll
            for (int ni = 0; ni < NT; ni++) {
                int rl = m0w + mi * 16 + gid;
                int cl = n0w + ni * 8 + tig * 2;
                float b0 = bias[col0 + cl];
                float b1 = bias[col0 + cl + 1];
                cs[rl * 132 + cl] = acc[mi][ni][0] + b0;
                cs[rl * 132 + cl + 1] = acc[mi][ni][1] + b1;
                cs[(rl + 8) * 132 + cl] = acc[mi][ni][2] + b0;
                cs[(rl + 8) * 132 + cl + 1] = acc[mi][ni][3] + b1;
            }
        __syncthreads();
        const int c = tid >> 1;                  // 0..127 column (h,d)
        const int sh = (tid & 1) * 64;           // s half
        const int gcol = col0 + c;
        const int h = gcol >> 6, d = gcol & 63;
        const int b = row0 >> 10, s0 = (row0 & 1023) + sh;
        size_t base = ((size_t)((b * 16 + h) * 64 + d) * S_ + s0);
        uint32_t* vh32 = (uint32_t*)(Vh + base);
        uint32_t* vl32 = (uint32_t*)(Vl + base);
        #pragma unroll
        for (int j = 0; j < 64; j += 2) {
            float v0 = cs[(sh + j) * 132 + c];
            float v1 = cs[(sh + j + 1) * 132 + c];
            uint32_t hp, lp;
            split_pack(v0, v1, hp, lp);
            vh32[j >> 1] = hp;
            vl32[j >> 1] = lp;
        }
    } else {
        #pragma unroll
        for (int mi = 0; mi < 2; mi++) {
            #pragma unroll
            for (int ni = 0; ni < NT; ni++) {
                int row = row0 + m0w + mi * 16 + gid;
                int col = col0 + n0w + ni * 8 + tig * 2;
                float b0 = bias ? bias[col] : 0.0f;
                float b1 = bias ? bias[col + 1] : 0.0f;
                float v0 = acc[mi][ni][0] * scale + b0;
                float v1 = acc[mi][ni][1] * scale + b1;
                float v2 = acc[mi][ni][2] * scale + b0;
                float v3 = acc[mi][ni][3] * scale + b1;
                if (MODE == 0) {
                    float2 o0 = {v0, v1}, o1 = {v2, v3};
                    *(float2*)&Cf[(size_t)row * ldc + col] = o0;
                    *(float2*)&Cf[(size_t)(row + 8) * ldc + col] = o1;
                } else {
                    uint32_t h0, l0, h1, l1;
                    split_pack(v0, v1, h0, l0);
                    split_pack(v2, v3, h1, l1);
                    size_t i0 = ((size_t)row * ldc + col) >> 1;
                    size_t i1 = ((size_t)(row + 8) * ldc + col) >> 1;
                    Ch[i0] = h0; Cl[i0] = l0;
                    Ch[i1] = h1; Cl[i1] = l1;
                }
            }
        }
    }
}

// ---------------- kernel wrappers ------------------------------------------
__global__ __launch_bounds__(256) void split_kernel(
        const float* __restrict__ src, uint32_t* __restrict__ hi,
        uint32_t* __restrict__ lo, int n4) {
    int idx = blockIdx.x * blockDim.x + threadIdx.x;
    if (idx >= n4) return;
    float4 v = ((const float4*)src)[idx];
    uint32_t h0, l0, h1, l1;
    split_pack(v.x, v.y, h0, l0);
    split_pack(v.z, v.w, h1, l1);
    uint2 hp = {h0, h1}, lp = {l0, l1};
    ((uint2*)hi)[idx] = hp;
    ((uint2*)lo)[idx] = lp;
}

__global__ __launch_bounds__(256) void proj_split_kernel(
        const __nv_bfloat16* Ah, const __nv_bfloat16* Al,
        const __nv_bfloat16* Bh, const __nv_bfloat16* Bl,
        const float* bias, uint32_t* Ch, uint32_t* Cl) {
    gemm_core<128, 1>(Ah, Al, W_, Bh, Bl, W_, W_, 1.0f, bias,
                      nullptr, Ch, Cl, W_, nullptr, nullptr);
}

__global__ __launch_bounds__(256) void proj_vt_kernel(
        const __nv_bfloat16* Ah, const __nv_bfloat16* Al,
        const __nv_bfloat16* Bh, const __nv_bfloat16* Bl,
        const float* bias, __nv_bfloat16* Vh, __nv_bfloat16* Vl) {
    gemm_core<128, 2>(Ah, Al, W_, Bh, Bl, W_, W_, 1.0f, bias,
                      nullptr, nullptr, nullptr, 0, Vh, Vl);
}

__global__ __launch_bounds__(256) void qk_kernel(
        const __nv_bfloat16* qh, const __nv_bfloat16* ql,
        const __nv_bfloat16* kh, const __nv_bfloat16* kl,
        float* __restrict__ out) {
    const int bh = blockIdx.z;
    const int b = bh >> 4, h = bh & 15;
    size_t off = (size_t)b * S_ * W_ + h * DH_;
    gemm_core<128, 0>(qh + off, ql + off, W_, kh + off, kl + off, W_,
                      DH_, 0.125f, nullptr,
                      out + (size_t)bh * S_ * S_, nullptr, nullptr, S_,
                      nullptr, nullptr);
}

__global__ __launch_bounds__(256) void av_kernel(
        const __nv_bfloat16* ah, const __nv_bfloat16* al,
        const __nv_bfloat16* vh, const __nv_bfloat16* vl,
        uint32_t* xh, uint32_t* xl) {
    const int bh = blockIdx.z;
    const int b = bh >> 4, h = bh & 15;
    size_t aoff = (size_t)bh * S_ * S_;
    size_t voff = (size_t)bh * DH_ * S_;
    size_t xoff = ((size_t)b * S_ * W_ + h * DH_) >> 1;
    gemm_core<64, 1>(ah + aoff, al + aoff, S_, vh + voff, vl + voff, S_,
                     S_, 1.0f, nullptr,
                     nullptr, xh + xoff, xl + xoff, W_, nullptr, nullptr);
}

__global__ __launch_bounds__(256) void out_kernel(
        const __nv_bfloat16* Ah, const __nv_bfloat16* Al,
        const __nv_bfloat16* Bh, const __nv_bfloat16* Bl,
        const float* bias, float* C) {
    gemm_core<128, 0>(Ah, Al, W_, Bh, Bl, W_, W_, 1.0f, bias,
                      C, nullptr, nullptr, W_, nullptr, nullptr);
}

// ---------------------------------------------------------------------------
// Head-axis softmax: read fp32 scores, write split-bf16 attn.
// Masked (b,q,k): all 16 logits equal -> uniform 1/16.
// ---------------------------------------------------------------------------
__global__ __launch_bounds__(256) void head_softmax_kernel(
        const int* __restrict__ mask, const float* __restrict__ qk,
        uint32_t* __restrict__ ath, uint32_t* __restrict__ atl) {
    const int idx = blockIdx.x * blockDim.x + threadIdx.x;   // over B*S*S/4
    const int b = idx >> 18;
    const int qs4 = idx & ((1 << 18) - 1);
    const size_t base = (size_t)b * H_ * S_ * S_ + (size_t)qs4 * 4;
    const size_t hs = (size_t)S_ * S_;

    int4 mv = ((const int4*)mask)[idx];
    int ms[4] = {mv.x, mv.y, mv.z, mv.w};

    float v[H_][4];
    #pragma unroll
    for (int h = 0; h < H_; h++) {
        float4 t = *(const float4*)&qk[base + h * hs];
        v[h][0] = t.x; v[h][1] = t.y; v[h][2] = t.z; v[h][3] = t.w;
    }

    #pragma unroll
    for (int l = 0; l < 4; l++) {
        if (ms[l] == 0) {
            #pragma unroll
            for (int h = 0; h < H_; h++) v[h][l] = 1.0f / 16.0f;
        } else {
            float mx = v[0][l];
            #pragma unroll
            for (int h = 1; h < H_; h++) mx = fmaxf(mx, v[h][l]);
            float s = 0.0f;
            #pragma unroll
            for (int h = 0; h < H_; h++) {
                v[h][l] = __expf(v[h][l] - mx);
                s += v[h][l];
            }
            float inv = 1.0f / s;
            #pragma unroll
            for (int h = 0; h < H_; h++) v[h][l] *= inv;
        }
    }

    #pragma unroll
    for (int h = 0; h < H_; h++) {
        uint32_t h0, l0, h1, l1;
        split_pack(v[h][0], v[h][1], h0, l0);
        split_pack(v[h][2], v[h][3], h1, l1);
        size_t i = (base + h * hs) >> 1;
        uint2 hp = {h0, h1}, lp = {l0, l1};
        *(uint2*)&ath[i] = hp;
        *(uint2*)&atl[i] = lp;
    }
}

// ---------------------------------------------------------------------------
extern "C" void kernel_launch(void* const* d_in, const int* in_sizes, int n_in,
                              void* d_out, int out_size) {
    const float* inp  = (const float*)d_in[0];
    const int*   mask = (const int*)  d_in[1];
    const float* wq   = (const float*)d_in[2];
    const float* bq   = (const float*)d_in[3];
    const float* wk   = (const float*)d_in[4];
    const float* bk   = (const float*)d_in[5];
    const float* wv   = (const float*)d_in[6];
    const float* bv   = (const float*)d_in[7];
    const float* wo   = (const float*)d_in[8];
    const float* bo   = (const float*)d_in[9];
    float* out = (float*)d_out;

    #define SYM(p, s) void* p; cudaGetSymbolAddress(&p, s)
    SYM(inp_h, g_inp_h); SYM(inp_l, g_inp_l);
    SYM(wq_h, g_wq_h);   SYM(wq_l, g_wq_l);
    SYM(wk_h, g_wk_h);   SYM(wk_l, g_wk_l);
    SYM(wv_h, g_wv_h);   SYM(wv_l, g_wv_l);
    SYM(wo_h, g_wo_h);   SYM(wo_l, g_wo_l);
    SYM(q_h, g_q_h);     SYM(q_l, g_q_l);
    SYM(k_h, g_k_h);     SYM(k_l, g_k_l);
    SYM(vt_h, g_vt_h);   SYM(vt_l, g_vt_l);
    SYM(x_h, g_x_h);     SYM(x_l, g_x_l);
    SYM(qkp, g_qk);
    SYM(at_h, g_at_h);   SYM(at_l, g_at_l);
    #undef SYM

    const int SMEM_BN128 = 81920;   // 80 KB
    const int SMEM_BN64  = 61440;   // 60 KB
    cudaFuncSetAttribute(proj_split_kernel, cudaFuncAttributeMaxDynamicSharedMemorySize, SMEM_BN128);
    cudaFuncSetAttribute(proj_vt_kernel,    cudaFuncAttributeMaxDynamicSharedMemorySize, SMEM_BN128);
    cudaFuncSetAttribute(qk_kernel,         cudaFuncAttributeMaxDynamicSharedMemorySize, SMEM_BN128);
    cudaFuncSetAttribute(out_kernel,        cudaFuncAttributeMaxDynamicSharedMemorySize, SMEM_BN128);
    cudaFuncSetAttribute(av_kernel,         cudaFuncAttributeMaxDynamicSharedMemorySize, SMEM_BN64);

    // 1) split inputs/weights to bf16 hi/lo
    split_kernel<<<(M_ * W_ / 4) / 256, 256>>>(inp, (uint32_t*)inp_h, (uint32_t*)inp_l, M_ * W_ / 4);
    split_kernel<<<(W_ * W_ / 4) / 256, 256>>>(wq, (uint32_t*)wq_h, (uint32_t*)wq_l, W_ * W_ / 4);
    split_kernel<<<(W_ * W_ / 4) / 256, 256>>>(wk, (uint32_t*)wk_h, (uint32_t*)wk_l, W_ * W_ / 4);
    split_kernel<<<(W_ * W_ / 4) / 256, 256>>>(wv, (uint32_t*)wv_h, (uint32_t*)wv_l, W_ * W_ / 4);
    split_kernel<<<(W_ * W_ / 4) / 256, 256>>>(wo, (uint32_t*)wo_h, (uint32_t*)wo_l, W_ * W_ / 4);

    dim3 pg(W_ / 128, M_ / 128);   // (8, 32)
    // 2) projections
    proj_split_kernel<<<pg, 256, SMEM_BN128>>>(
        (const __nv_bfloat16*)inp_h, (const __nv_bfloat16*)inp_l,
        (const __nv_bfloat16*)wq_h,  (const __nv_bfloat16*)wq_l,
        bq, (uint32_t*)q_h, (uint32_t*)q_l);
    proj_split_kernel<<<pg, 256, SMEM_BN128>>>(
        (const __nv_bfloat16*)inp_h, (const __nv_bfloat16*)inp_l,
        (const __nv_bfloat16*)wk_h,  (const __nv_bfloat16*)wk_l,
        bk, (uint32_t*)k_h, (uint32_t*)k_l);
    proj_vt_kernel<<<pg, 256, SMEM_BN128>>>(
        (const __nv_bfloat16*)inp_h, (const __nv_bfloat16*)inp_l,
        (const __nv_bfloat16*)wv_h,  (const __nv_bfloat16*)wv_l,
        bv, (__nv_bfloat16*)vt_h, (__nv_bfloat16*)vt_l);

    // 3) QK^T
    dim3 qg(S_ / 128, S_ / 128, B_ * H_);   // (8, 8, 64)
    qk_kernel<<<qg, 256, SMEM_BN128>>>(
        (const __nv_bfloat16*)q_h, (const __nv_bfloat16*)q_l,
        (const __nv_bfloat16*)k_h, (const __nv_bfloat16*)k_l, (float*)qkp);

    // 4) head-axis softmax -> split bf16 attn
    head_softmax_kernel<<<(B_ * S_ * S_ / 4) / 256, 256>>>(
        mask, (const float*)qkp, (uint32_t*)at_h, (uint32_t*)at_l);

    // 5) attn @ V -> x (split bf16)
    dim3 ag(1, S_ / 128, B_ * H_);
    av_kernel<<<ag, 256, SMEM_BN64>>>(
        (const __nv_bfloat16*)at_h, (const __nv_bfloat16*)at_l,
        (const __nv_bfloat16*)vt_h, (const __nv_bfloat16*)vt_l,
        (uint32_t*)x_h, (uint32_t*)x_l);

    // 6) output projection (fp32 out + bias)
    out_kernel<<<pg, 256, SMEM_BN128>>>(
        (const __nv_bfloat16*)x_h, (const __nv_bfloat16*)x_l,
        (const __nv_bfloat16*)wo_h, (const __nv_bfloat16*)wo_l,
        bo, out);
}